// round 1
// baseline (speedup 1.0000x reference)
#include <cuda_runtime.h>

#define TT   2048
#define NB   8
#define DIMK 1024
#define HIDN 128

typedef unsigned long long u64;

// Scratch (static __device__ allocations are allowed; runtime allocs are not)
__device__ float g_ewT[TT * TT];  // ewT[s][t] = exp(w[t][s])
__device__ float g_z[TT * TT];    // z[s][b*256 + 2h] = exp(K)*V ; z[s][b*256+2h+1] = exp(K)

// ---------------- packed f32x2 helpers (Blackwell FFMA2 path) ----------------
__device__ __forceinline__ u64 pk2(float lo, float hi) {
    u64 r; asm("mov.b64 %0, {%1,%2};" : "=l"(r) : "f"(lo), "f"(hi)); return r;
}
__device__ __forceinline__ float2 upk2(u64 v) {
    float2 f; asm("mov.b64 {%0,%1}, %2;" : "=f"(f.x), "=f"(f.y) : "l"(v)); return f;
}
__device__ __forceinline__ void fma2(u64& d, u64 a, u64 b) {
    asm("fma.rn.f32x2 %0, %1, %2, %0;" : "+l"(d) : "l"(a), "l"(b));
}

// ---------------- Kernel 1: ewT[s][t] = exp(w[t][s]) (tiled transpose) -------
__global__ void k_expw(const float* __restrict__ w) {
    __shared__ float tile[32][33];
    const int bx = blockIdx.x << 5;  // s block
    const int by = blockIdx.y << 5;  // t block
    const int tx = threadIdx.x, ty = threadIdx.y;
#pragma unroll
    for (int i = 0; i < 32; i += 8)
        tile[ty + i][tx] = w[(by + ty + i) * TT + bx + tx];
    __syncthreads();
#pragma unroll
    for (int i = 0; i < 32; i += 8)
        g_ewT[(bx + ty + i) * TT + by + tx] = __expf(tile[tx][ty + i]);
}

// ---------------- Kernel 2: projection GEMM + exp epilogue -------------------
// P = x[16384,1024] @ Wcat[1024,256] (+bias), where Wcat columns are interleaved
// (wk_h, wv_h) pairs. Epilogue writes g_z[t][b*256 + cn] with cn even = eK*V,
// cn odd = eK.
__global__ __launch_bounds__(256, 2) void k_proj(
    const float* __restrict__ x, const float* __restrict__ wk,
    const float* __restrict__ bk, const float* __restrict__ wv,
    const float* __restrict__ bv) {
    __shared__ float As[16][132];  // As[k][m]
    __shared__ float Bs[16][128];  // Bs[k][n_local] interleaved K/V

    const int tid = threadIdx.x;
    const int m0 = blockIdx.x << 7;   // 0..16383 in steps of 128
    const int n0 = blockIdx.y << 7;   // 0 or 128
    const int tm0 = (tid >> 4) << 3;
    const int tn0 = (tid & 15) << 3;

    u64 acc[4][8];
#pragma unroll
    for (int i = 0; i < 4; i++)
#pragma unroll
        for (int j = 0; j < 8; j++) acc[i][j] = 0ULL;

    // A load mapping: per thread two float4 rows (m, m+64), k-quad = tid&3
    const int a_m = tid >> 2;      // 0..63
    const int a_kq = (tid & 3) * 4;
    // B load mapping: k row = tid>>4, 8 interleaved columns
    const int b_k = tid >> 4;
    const int b_nl0 = (tid & 15) << 3;

    float4 a0r, a1r;
    float bkv[8];

    // prologue: tile kt = 0
    a0r = *(const float4*)(x + (m0 + a_m) * DIMK + a_kq);
    a1r = *(const float4*)(x + (m0 + a_m + 64) * DIMK + a_kq);
#pragma unroll
    for (int p = 0; p < 4; p++) {
        int h = (n0 + b_nl0 + 2 * p) >> 1;
        bkv[2 * p] = wk[b_k * HIDN + h];
        bkv[2 * p + 1] = wv[b_k * HIDN + h];
    }

    for (int kt = 0; kt < DIMK; kt += 16) {
        __syncthreads();
        As[a_kq + 0][a_m] = a0r.x;
        As[a_kq + 1][a_m] = a0r.y;
        As[a_kq + 2][a_m] = a0r.z;
        As[a_kq + 3][a_m] = a0r.w;
        As[a_kq + 0][a_m + 64] = a1r.x;
        As[a_kq + 1][a_m + 64] = a1r.y;
        As[a_kq + 2][a_m + 64] = a1r.z;
        As[a_kq + 3][a_m + 64] = a1r.w;
#pragma unroll
        for (int e = 0; e < 8; e++) Bs[b_k][b_nl0 + e] = bkv[e];
        __syncthreads();

        if (kt + 16 < DIMK) {
            const int kn = kt + 16;
            a0r = *(const float4*)(x + (m0 + a_m) * DIMK + kn + a_kq);
            a1r = *(const float4*)(x + (m0 + a_m + 64) * DIMK + kn + a_kq);
#pragma unroll
            for (int p = 0; p < 4; p++) {
                int h = (n0 + b_nl0 + 2 * p) >> 1;
                bkv[2 * p] = wk[(kn + b_k) * HIDN + h];
                bkv[2 * p + 1] = wv[(kn + b_k) * HIDN + h];
            }
        }

#pragma unroll
        for (int kk = 0; kk < 16; kk++) {
            u64 ap0 = *(const u64*)&As[kk][tm0 + 0];
            u64 ap1 = *(const u64*)&As[kk][tm0 + 2];
            u64 ap2 = *(const u64*)&As[kk][tm0 + 4];
            u64 ap3 = *(const u64*)&As[kk][tm0 + 6];
            float4 b0 = *(const float4*)&Bs[kk][tn0];
            float4 b1 = *(const float4*)&Bs[kk][tn0 + 4];
            float bb[8] = {b0.x, b0.y, b0.z, b0.w, b1.x, b1.y, b1.z, b1.w};
#pragma unroll
            for (int j = 0; j < 8; j++) {
                u64 bj = pk2(bb[j], bb[j]);
                fma2(acc[0][j], ap0, bj);
                fma2(acc[1][j], ap1, bj);
                fma2(acc[2][j], ap2, bj);
                fma2(acc[3][j], ap3, bj);
            }
        }
    }

    // epilogue: add bias, exp, interleaved write into g_z
#pragma unroll
    for (int i2 = 0; i2 < 4; i2++) {
        float lo[8], hi[8];
#pragma unroll
        for (int j = 0; j < 8; j++) {
            float2 f = upk2(acc[i2][j]);
            lo[j] = f.x; hi[j] = f.y;
        }
#pragma unroll
        for (int r = 0; r < 2; r++) {
            const float* vals = r ? hi : lo;
            int m = m0 + tm0 + 2 * i2 + r;  // row in x-flat: m = b*2048 + t
            int b = m >> 11;
            int t = m & 2047;
            float ov[8];
#pragma unroll
            for (int p = 0; p < 4; p++) {
                int h = (n0 + tn0 + 2 * p) >> 1;
                float Kv = vals[2 * p] + bk[h];
                float Vv = vals[2 * p + 1] + bv[h];
                float ek = __expf(Kv);
                ov[2 * p] = ek * Vv;
                ov[2 * p + 1] = ek;
            }
            float* dst = g_z + t * TT + b * 256 + n0 + tn0;
            *(float4*)(dst) = make_float4(ov[0], ov[1], ov[2], ov[3]);
            *(float4*)(dst + 4) = make_float4(ov[4], ov[5], ov[6], ov[7]);
        }
    }
}

// ---------------- Kernel 3: Y = ew @ z, epilogue out = num/den ---------------
// A = g_ewT (stored K-major: ewT[s][t]), B = g_z[s][col]. Both tile loads are
// row-contiguous -> fully coalesced float4, direct STS, no transpose.
__global__ __launch_bounds__(256, 2) void k_main(float* __restrict__ out) {
    __shared__ float As[16][132];
    __shared__ float Bs[16][128];

    const int tid = threadIdx.x;
    const int m0 = blockIdx.x << 7;  // t block
    const int n0 = blockIdx.y << 7;  // col block
    const int tm0 = (tid >> 4) << 3;
    const int tn0 = (tid & 15) << 3;

    u64 acc[4][8];
#pragma unroll
    for (int i = 0; i < 4; i++)
#pragma unroll
        for (int j = 0; j < 8; j++) acc[i][j] = 0ULL;

    const int l_k = tid >> 5;       // 0..7 (second load: +8)
    const int l_q = (tid & 31) * 4; // float4 column

    float4 aA, aB, bA, bB;
    aA = *(const float4*)(g_ewT + (l_k) * TT + m0 + l_q);
    aB = *(const float4*)(g_ewT + (l_k + 8) * TT + m0 + l_q);
    bA = *(const float4*)(g_z + (l_k) * TT + n0 + l_q);
    bB = *(const float4*)(g_z + (l_k + 8) * TT + n0 + l_q);

    for (int kt = 0; kt < TT; kt += 16) {
        __syncthreads();
        *(float4*)&As[l_k][l_q] = aA;
        *(float4*)&As[l_k + 8][l_q] = aB;
        *(float4*)&Bs[l_k][l_q] = bA;
        *(float4*)&Bs[l_k + 8][l_q] = bB;
        __syncthreads();

        if (kt + 16 < TT) {
            const int kn = kt + 16;
            aA = *(const float4*)(g_ewT + (kn + l_k) * TT + m0 + l_q);
            aB = *(const float4*)(g_ewT + (kn + l_k + 8) * TT + m0 + l_q);
            bA = *(const float4*)(g_z + (kn + l_k) * TT + n0 + l_q);
            bB = *(const float4*)(g_z + (kn + l_k + 8) * TT + n0 + l_q);
        }

#pragma unroll
        for (int kk = 0; kk < 16; kk++) {
            u64 ap0 = *(const u64*)&As[kk][tm0 + 0];
            u64 ap1 = *(const u64*)&As[kk][tm0 + 2];
            u64 ap2 = *(const u64*)&As[kk][tm0 + 4];
            u64 ap3 = *(const u64*)&As[kk][tm0 + 6];
            float4 b0 = *(const float4*)&Bs[kk][tn0];
            float4 b1 = *(const float4*)&Bs[kk][tn0 + 4];
            float bb[8] = {b0.x, b0.y, b0.z, b0.w, b1.x, b1.y, b1.z, b1.w};
#pragma unroll
            for (int j = 0; j < 8; j++) {
                u64 bj = pk2(bb[j], bb[j]);
                fma2(acc[0][j], ap0, bj);
                fma2(acc[1][j], ap1, bj);
                fma2(acc[2][j], ap2, bj);
                fma2(acc[3][j], ap3, bj);
            }
        }
    }

    // epilogue: num/den, write out[b][t][h]
    const int cn0 = n0 + tn0;
    const int b = cn0 >> 8;
    const int h0 = (cn0 & 255) >> 1;
#pragma unroll
    for (int i2 = 0; i2 < 4; i2++) {
        float lo[8], hi[8];
#pragma unroll
        for (int j = 0; j < 8; j++) {
            float2 f = upk2(acc[i2][j]);
            lo[j] = f.x; hi[j] = f.y;
        }
#pragma unroll
        for (int r = 0; r < 2; r++) {
            const float* vals = r ? hi : lo;
            int t = m0 + tm0 + 2 * i2 + r;
            float4 o;
            o.x = vals[0] / vals[1];
            o.y = vals[2] / vals[3];
            o.z = vals[4] / vals[5];
            o.w = vals[6] / vals[7];
            *(float4*)(out + (b * TT + t) * HIDN + h0) = o;
        }
    }
}

// ---------------- launch ----------------
extern "C" void kernel_launch(void* const* d_in, const int* in_sizes, int n_in,
                              void* d_out, int out_size) {
    const float* x  = (const float*)d_in[0];
    const float* wk = (const float*)d_in[1];
    const float* bk = (const float*)d_in[2];
    const float* wv = (const float*)d_in[3];
    const float* bv = (const float*)d_in[4];
    const float* w  = (const float*)d_in[5];
    float* out = (float*)d_out;

    k_expw<<<dim3(64, 64), dim3(32, 8)>>>(w);
    k_proj<<<dim3(128, 2), 256>>>(x, wk, bk, wv, bv);
    k_main<<<dim3(16, 16), 256>>>(out);
}

// round 3
// speedup vs baseline: 1.3719x; 1.3719x over previous
#include <cuda_runtime.h>
#include <cuda_bf16.h>
#include <cstdint>

#define TT   2048
#define DIMK 1024
#define HIDN 128

typedef unsigned long long u64;
typedef unsigned int u32;

// ---------------- scratch (__device__ globals; no runtime alloc) ------------
__device__ float         g_z[TT * TT];    // z[s][b*256+2h]=eK*V, [..2h+1]=eK
__device__ __nv_bfloat16 g_Ah[TT * TT];   // A hi: exp(w)[t][s]  (K-major rows)
__device__ __nv_bfloat16 g_Al[TT * TT];   // A lo
__device__ __nv_bfloat16 g_Bh[TT * TT];   // B hi: zT[col][s]    (K-major rows)
__device__ __nv_bfloat16 g_Bl[TT * TT];   // B lo

// ---------------- packed f32x2 helpers (FFMA2 path for k_proj) --------------
__device__ __forceinline__ u64 pk2(float lo, float hi) {
    u64 r; asm("mov.b64 %0, {%1,%2};" : "=l"(r) : "f"(lo), "f"(hi)); return r;
}
__device__ __forceinline__ float2 upk2(u64 v) {
    float2 f; asm("mov.b64 {%0,%1}, %2;" : "=f"(f.x), "=f"(f.y) : "l"(v)); return f;
}
__device__ __forceinline__ void fma2(u64& d, u64 a, u64 b) {
    asm("fma.rn.f32x2 %0, %1, %2, %0;" : "+l"(d) : "l"(a), "l"(b));
}

// ---------------- async-copy / mma helpers (baseline PTX, sm_80+) -----------
__device__ __forceinline__ u32 smem_u32(const void* p) {
    u32 a;
    asm("{ .reg .u64 t; cvta.to.shared.u64 t, %1; cvt.u32.u64 %0, t; }"
        : "=r"(a) : "l"(p));
    return a;
}
__device__ __forceinline__ void cp16(u32 s, const void* g) {
    asm volatile("cp.async.cg.shared.global [%0], [%1], 16;" :: "r"(s), "l"(g));
}
#define CP_COMMIT() asm volatile("cp.async.commit_group;" ::: "memory")
#define CP_WAIT2()  asm volatile("cp.async.wait_group 2;" ::: "memory")

__device__ __forceinline__ void ldsm4(u32 addr, u32& r0, u32& r1, u32& r2, u32& r3) {
    asm volatile("ldmatrix.sync.aligned.m8n8.x4.shared.b16 {%0,%1,%2,%3}, [%4];"
                 : "=r"(r0), "=r"(r1), "=r"(r2), "=r"(r3) : "r"(addr));
}
__device__ __forceinline__ void mma16816(float* d, u32 a0, u32 a1, u32 a2, u32 a3,
                                         u32 b0, u32 b1) {
    asm volatile(
        "mma.sync.aligned.m16n8k16.row.col.f32.bf16.bf16.f32 "
        "{%0,%1,%2,%3}, {%4,%5,%6,%7}, {%8,%9}, {%0,%1,%2,%3};"
        : "+f"(d[0]), "+f"(d[1]), "+f"(d[2]), "+f"(d[3])
        : "r"(a0), "r"(a1), "r"(a2), "r"(a3), "r"(b0), "r"(b1));
}

// ---------------- Kernel 1: exp(w) -> A hi/lo (elementwise) -----------------
__global__ void k_expw2(const float* __restrict__ w) {
    int i = blockIdx.x * blockDim.x + threadIdx.x;  // float4 index
    float4 v = ((const float4*)w)[i];
    float e[4] = {__expf(v.x), __expf(v.y), __expf(v.z), __expf(v.w)};
    ushort4 H, L;
    unsigned short* hp = &H.x;
    unsigned short* lp = &L.x;
#pragma unroll
    for (int q = 0; q < 4; q++) {
        __nv_bfloat16 h = __float2bfloat16(e[q]);
        __nv_bfloat16 l = __float2bfloat16(e[q] - __bfloat162float(h));
        hp[q] = __bfloat16_as_ushort(h);
        lp[q] = __bfloat16_as_ushort(l);
    }
    ((ushort4*)g_Ah)[i] = H;
    ((ushort4*)g_Al)[i] = L;
}

// ---------------- Kernel 2: projection GEMM + exp epilogue (FFMA2) ----------
__global__ __launch_bounds__(256, 2) void k_proj(
    const float* __restrict__ x, const float* __restrict__ wk,
    const float* __restrict__ bk, const float* __restrict__ wv,
    const float* __restrict__ bv) {
    __shared__ float As[16][132];
    __shared__ float Bs[16][128];

    const int tid = threadIdx.x;
    const int m0 = blockIdx.x << 7;
    const int n0 = blockIdx.y << 7;
    const int tm0 = (tid >> 4) << 3;
    const int tn0 = (tid & 15) << 3;

    u64 acc[4][8];
#pragma unroll
    for (int i = 0; i < 4; i++)
#pragma unroll
        for (int j = 0; j < 8; j++) acc[i][j] = 0ULL;

    const int a_m = tid >> 2;
    const int a_kq = (tid & 3) * 4;
    const int b_k = tid >> 4;
    const int b_nl0 = (tid & 15) << 3;

    float4 a0r, a1r;
    float bkv[8];

    a0r = *(const float4*)(x + (m0 + a_m) * DIMK + a_kq);
    a1r = *(const float4*)(x + (m0 + a_m + 64) * DIMK + a_kq);
#pragma unroll
    for (int p = 0; p < 4; p++) {
        int h = (n0 + b_nl0 + 2 * p) >> 1;
        bkv[2 * p] = wk[b_k * HIDN + h];
        bkv[2 * p + 1] = wv[b_k * HIDN + h];
    }

    for (int kt = 0; kt < DIMK; kt += 16) {
        __syncthreads();
        As[a_kq + 0][a_m] = a0r.x;
        As[a_kq + 1][a_m] = a0r.y;
        As[a_kq + 2][a_m] = a0r.z;
        As[a_kq + 3][a_m] = a0r.w;
        As[a_kq + 0][a_m + 64] = a1r.x;
        As[a_kq + 1][a_m + 64] = a1r.y;
        As[a_kq + 2][a_m + 64] = a1r.z;
        As[a_kq + 3][a_m + 64] = a1r.w;
#pragma unroll
        for (int e = 0; e < 8; e++) Bs[b_k][b_nl0 + e] = bkv[e];
        __syncthreads();

        if (kt + 16 < DIMK) {
            const int kn = kt + 16;
            a0r = *(const float4*)(x + (m0 + a_m) * DIMK + kn + a_kq);
            a1r = *(const float4*)(x + (m0 + a_m + 64) * DIMK + kn + a_kq);
#pragma unroll
            for (int p = 0; p < 4; p++) {
                int h = (n0 + b_nl0 + 2 * p) >> 1;
                bkv[2 * p] = wk[(kn + b_k) * HIDN + h];
                bkv[2 * p + 1] = wv[(kn + b_k) * HIDN + h];
            }
        }

#pragma unroll
        for (int kk = 0; kk < 16; kk++) {
            u64 ap0 = *(const u64*)&As[kk][tm0 + 0];
            u64 ap1 = *(const u64*)&As[kk][tm0 + 2];
            u64 ap2 = *(const u64*)&As[kk][tm0 + 4];
            u64 ap3 = *(const u64*)&As[kk][tm0 + 6];
            float4 b0 = *(const float4*)&Bs[kk][tn0];
            float4 b1 = *(const float4*)&Bs[kk][tn0 + 4];
            float bb[8] = {b0.x, b0.y, b0.z, b0.w, b1.x, b1.y, b1.z, b1.w};
#pragma unroll
            for (int j = 0; j < 8; j++) {
                u64 bj = pk2(bb[j], bb[j]);
                fma2(acc[0][j], ap0, bj);
                fma2(acc[1][j], ap1, bj);
                fma2(acc[2][j], ap2, bj);
                fma2(acc[3][j], ap3, bj);
            }
        }
    }

#pragma unroll
    for (int i2 = 0; i2 < 4; i2++) {
        float lo[8], hi[8];
#pragma unroll
        for (int j = 0; j < 8; j++) {
            float2 f = upk2(acc[i2][j]);
            lo[j] = f.x; hi[j] = f.y;
        }
#pragma unroll
        for (int r = 0; r < 2; r++) {
            const float* vals = r ? hi : lo;
            int m = m0 + tm0 + 2 * i2 + r;
            int b = m >> 11;
            int t = m & 2047;
            float ov[8];
#pragma unroll
            for (int p = 0; p < 4; p++) {
                int h = (n0 + tn0 + 2 * p) >> 1;
                float Kv = vals[2 * p] + bk[h];
                float Vv = vals[2 * p + 1] + bv[h];
                float ek = __expf(Kv);
                ov[2 * p] = ek * Vv;
                ov[2 * p + 1] = ek;
            }
            float* dst = g_z + t * TT + b * 256 + n0 + tn0;
            *(float4*)(dst) = make_float4(ov[0], ov[1], ov[2], ov[3]);
            *(float4*)(dst + 4) = make_float4(ov[4], ov[5], ov[6], ov[7]);
        }
    }
}

// ---------------- Kernel 3: transpose+split z -> B hi/lo --------------------
__global__ void k_zT() {
    __shared__ float tile[32][33];
    const int bc = blockIdx.x << 5;  // col block
    const int bs = blockIdx.y << 5;  // s block
    const int tx = threadIdx.x, ty = threadIdx.y;
#pragma unroll
    for (int i = 0; i < 32; i += 8)
        tile[ty + i][tx] = g_z[(size_t)(bs + ty + i) * TT + bc + tx];
    __syncthreads();
#pragma unroll
    for (int i = 0; i < 32; i += 8) {
        float v = tile[tx][ty + i];
        __nv_bfloat16 h = __float2bfloat16(v);
        __nv_bfloat16 l = __float2bfloat16(v - __bfloat162float(h));
        size_t o = (size_t)(bc + ty + i) * TT + bs + tx;
        g_Bh[o] = h;
        g_Bl[o] = l;
    }
}

// ---------------- Kernel 4: bf16x3 main GEMM via mma.sync (HMMA) ------------
// C[t][col] = sum_s ew[t][s]*z[s][col];  out = C[:,even]/C[:,odd]
#define ROWB   80                 // smem bytes per 32-elem bf16 row (pad 8)
#define MATB   (128 * ROWB)       // 10240 B per operand tile
#define STAGEB (4 * MATB)         // Ah, Al, Bh, Bl
#define NSTAGE 3
#define SMEMTOT (NSTAGE * STAGEB) // 122880 B
#define NCH    (TT / 32)          // 64 k-chunks of 32

__device__ __forceinline__ void load_stage(u32 sb, int stage, int m0, int n0,
                                           int chunk, int tid) {
    const u32 dst = sb + (u32)stage * STAGEB;
    const int r = tid >> 1;
    const int ko0 = (tid & 1) * 2;
    const size_t cb = (size_t)chunk * 64;
    const char* pAh = (const char*)g_Ah + (size_t)(m0 + r) * 4096 + cb;
    const char* pAl = (const char*)g_Al + (size_t)(m0 + r) * 4096 + cb;
    const char* pBh = (const char*)g_Bh + (size_t)(n0 + r) * 4096 + cb;
    const char* pBl = (const char*)g_Bl + (size_t)(n0 + r) * 4096 + cb;
    const u32 ro = (u32)r * ROWB;
#pragma unroll
    for (int i = 0; i < 2; i++) {
        const int ko = ko0 + i;
        const u32 so = ro + (u32)ko * 16;
        cp16(dst + 0 * MATB + so, pAh + ko * 16);
        cp16(dst + 1 * MATB + so, pAl + ko * 16);
        cp16(dst + 2 * MATB + so, pBh + ko * 16);
        cp16(dst + 3 * MATB + so, pBl + ko * 16);
    }
}

__global__ __launch_bounds__(256) void k_mainTC(float* __restrict__ out) {
    extern __shared__ char smem[];
    const u32 sb = smem_u32(smem);
    const int tid = threadIdx.x;
    const int wid = tid >> 5, lane = tid & 31;
    const int m0 = blockIdx.x << 7;
    const int n0 = blockIdx.y << 7;
    const int warp_m = wid >> 2;            // 0..1
    const int warp_n = wid & 3;             // 0..3
    const int m_base = warp_m * 64;
    const int n_base = warp_n * 32;

    float acc[4][4][4];
#pragma unroll
    for (int i = 0; i < 4; i++)
#pragma unroll
        for (int j = 0; j < 4; j++)
#pragma unroll
            for (int q = 0; q < 4; q++) acc[i][j][q] = 0.0f;

    // ldmatrix lane-address offsets (within an operand tile)
    const u32 aoff = (u32)(m_base + (lane & 15)) * ROWB + (u32)(lane >> 4) * 16;
    const u32 boff = (u32)(n_base + (lane & 7) + ((lane >> 4) << 3)) * ROWB +
                     (u32)((lane >> 3) & 1) * 16;

    // prologue: 3 stages in flight
    load_stage(sb, 0, m0, n0, 0, tid); CP_COMMIT();
    load_stage(sb, 1, m0, n0, 1, tid); CP_COMMIT();
    load_stage(sb, 2, m0, n0, 2, tid); CP_COMMIT();

#pragma unroll 1
    for (int c = 0; c < NCH; c++) {
        CP_WAIT2();
        __syncthreads();

        const u32 s0 = sb + (u32)(c % 3) * STAGEB;
#pragma unroll
        for (int ks = 0; ks < 2; ks++) {
            const u32 ak = aoff + (u32)ks * 32;
            const u32 bk = boff + (u32)ks * 32;

            u32 Af[4][4];  // A fragments (hi first, then overwritten by lo)
            u32 Bf[2][4];  // B fragments (2 ldmatrix.x4 = 4 n8-tiles)

#pragma unroll
            for (int mt = 0; mt < 4; mt++)
                ldsm4(s0 + 0 * MATB + ak + (u32)mt * (16 * ROWB),
                      Af[mt][0], Af[mt][1], Af[mt][2], Af[mt][3]);
#pragma unroll
            for (int np = 0; np < 2; np++)
                ldsm4(s0 + 2 * MATB + bk + (u32)np * (16 * ROWB),
                      Bf[np][0], Bf[np][1], Bf[np][2], Bf[np][3]);
            // pass 1: Ah * Bh
#pragma unroll
            for (int mt = 0; mt < 4; mt++)
#pragma unroll
                for (int nt = 0; nt < 4; nt++)
                    mma16816(acc[mt][nt], Af[mt][0], Af[mt][1], Af[mt][2], Af[mt][3],
                             Bf[nt >> 1][(nt & 1) * 2], Bf[nt >> 1][(nt & 1) * 2 + 1]);
            // pass 2: Ah * Bl
#pragma unroll
            for (int np = 0; np < 2; np++)
                ldsm4(s0 + 3 * MATB + bk + (u32)np * (16 * ROWB),
                      Bf[np][0], Bf[np][1], Bf[np][2], Bf[np][3]);
#pragma unroll
            for (int mt = 0; mt < 4; mt++)
#pragma unroll
                for (int nt = 0; nt < 4; nt++)
                    mma16816(acc[mt][nt], Af[mt][0], Af[mt][1], Af[mt][2], Af[mt][3],
                             Bf[nt >> 1][(nt & 1) * 2], Bf[nt >> 1][(nt & 1) * 2 + 1]);
            // pass 3: Al * Bh
#pragma unroll
            for (int mt = 0; mt < 4; mt++)
                ldsm4(s0 + 1 * MATB + ak + (u32)mt * (16 * ROWB),
                      Af[mt][0], Af[mt][1], Af[mt][2], Af[mt][3]);
#pragma unroll
            for (int np = 0; np < 2; np++)
                ldsm4(s0 + 2 * MATB + bk + (u32)np * (16 * ROWB),
                      Bf[np][0], Bf[np][1], Bf[np][2], Bf[np][3]);
#pragma unroll
            for (int mt = 0; mt < 4; mt++)
#pragma unroll
                for (int nt = 0; nt < 4; nt++)
                    mma16816(acc[mt][nt], Af[mt][0], Af[mt][1], Af[mt][2], Af[mt][3],
                             Bf[nt >> 1][(nt & 1) * 2], Bf[nt >> 1][(nt & 1) * 2 + 1]);
        }

        __syncthreads();
        if (c + 3 < NCH) {
            load_stage(sb, c % 3, m0, n0, c + 3, tid);
            CP_COMMIT();
        }
    }

    // epilogue: out = num/den from register accumulators
#pragma unroll
    for (int mt = 0; mt < 4; mt++) {
        const int t0 = m0 + m_base + mt * 16 + (lane >> 2);
#pragma unroll
        for (int nt = 0; nt < 4; nt++) {
            const int gcol = n0 + n_base + nt * 8 + 2 * (lane & 3);
            const int b = gcol >> 8;
            const int h = (gcol & 255) >> 1;
            float* o0 = out + ((size_t)(b * TT + t0)) * HIDN + h;
            o0[0] = __fdividef(acc[mt][nt][0], acc[mt][nt][1]);
            o0[8 * HIDN] = __fdividef(acc[mt][nt][2], acc[mt][nt][3]);
        }
    }
}

// ---------------- launch ----------------
extern "C" void kernel_launch(void* const* d_in, const int* in_sizes, int n_in,
                              void* d_out, int out_size) {
    const float* x  = (const float*)d_in[0];
    const float* wk = (const float*)d_in[1];
    const float* bk = (const float*)d_in[2];
    const float* wv = (const float*)d_in[3];
    const float* bv = (const float*)d_in[4];
    const float* w  = (const float*)d_in[5];
    float* out = (float*)d_out;

    cudaFuncSetAttribute(k_mainTC, cudaFuncAttributeMaxDynamicSharedMemorySize,
                         SMEMTOT);

    k_expw2<<<4096, 256>>>(w);
    k_proj<<<dim3(128, 2), 256>>>(x, wk, bk, wv, bv);
    k_zT<<<dim3(64, 64), dim3(32, 8)>>>();
    k_mainTC<<<dim3(16, 16), 256, SMEMTOT>>>(out);
}